// round 8
// baseline (speedup 1.0000x reference)
#include <cuda_runtime.h>

// Problem constants (match reference)
#define B   16
#define LX  2048
#define LR  1024
#define D   768
#define T   (LX + LR + 3)      // 3075
#define D4  (D / 4)            // 192 float4 per row
#define NROWS   (B * T)        // 49200
#define NCHUNK  (NROWS * D4)   // 9,446,400 float4 chunks
#define TPB     256
#define UNROLL  4

// out[b,t,:] =
//   t == 0                          : CLS
//   1 <= t <= lx[b]                 : X[b, t-1]
//   t == lx[b]+1                    : RING
//   lx[b]+2 <= t < lx[b]+2+lr[b]    : Xr[b, t-lx[b]-2]
//   t == lx[b]+lr[b]+2              : END
//   else                            : 0
//
// Persistent grid-stride kernel: grid sized to exactly fill the chip (no
// wave-quantization tail, one resident wave does all work). Streaming
// cache policy on both sides (__ldcs/__stcs) — empirically best in the
// steady-state replay loop. Inner unroll-4 keeps 4 independent gathers in
// flight before any store.
__device__ __forceinline__ float4 gather_one(
    int idx,
    const float4* __restrict__ X,
    const float4* __restrict__ Xr,
    const float4* __restrict__ CLS,
    const float4* __restrict__ RING,
    const float4* __restrict__ END,
    const int*    __restrict__ lx,
    const int*    __restrict__ lr)
{
    const int row = idx / D4;          // const-div -> mul/shift
    const int c   = idx - row * D4;
    const int b   = row / T;
    const int t   = row - b * T;

    const int lxb = __ldg(&lx[b]);
    const int lrb = __ldg(&lr[b]);

    if (t == 0)                 return CLS[c];
    if (t <= lxb)               return __ldcs(&X[((long)b * LX + (t - 1)) * D4 + c]);
    if (t == lxb + 1)           return RING[c];
    if (t < lxb + 2 + lrb)      return __ldcs(&Xr[((long)b * LR + (t - lxb - 2)) * D4 + c]);
    if (t == lxb + lrb + 2)     return END[c];
    return make_float4(0.f, 0.f, 0.f, 0.f);
}

__global__ __launch_bounds__(TPB) void assemble_kernel(
    const float4* __restrict__ X,
    const float4* __restrict__ Xr,
    const float4* __restrict__ CLS,
    const float4* __restrict__ RING,
    const float4* __restrict__ END,
    const int*    __restrict__ lx,
    const int*    __restrict__ lr,
    float4*       __restrict__ out)
{
    const int nth   = gridDim.x * TPB;          // total threads
    int idx0 = blockIdx.x * TPB + threadIdx.x;

    // Main unrolled loop: 4 independent chunks per iteration.
    const long stride = (long)nth * UNROLL;
    long base = idx0;
    for (; base + (long)(UNROLL - 1) * nth < NCHUNK; base += stride) {
        float4 v[UNROLL];
        #pragma unroll
        for (int k = 0; k < UNROLL; k++)
            v[k] = gather_one((int)(base + (long)k * nth), X, Xr, CLS, RING, END, lx, lr);
        #pragma unroll
        for (int k = 0; k < UNROLL; k++)
            __stcs(&out[base + (long)k * nth], v[k]);
    }
    // Remainder
    for (; base < NCHUNK; base += nth) {
        float4 v = gather_one((int)base, X, Xr, CLS, RING, END, lx, lr);
        __stcs(&out[base], v);
    }
}

extern "C" void kernel_launch(void* const* d_in, const int* in_sizes, int n_in,
                              void* d_out, int out_size)
{
    const float4* X    = (const float4*)d_in[0];
    const float4* Xr   = (const float4*)d_in[1];
    const float4* CLS  = (const float4*)d_in[2];
    const float4* RING = (const float4*)d_in[3];
    const float4* END  = (const float4*)d_in[4];
    const int*    lx   = (const int*)d_in[5];
    const int*    lr   = (const int*)d_in[6];
    float4*       out  = (float4*)d_out;

    int sms = 148;
    cudaDeviceGetAttribute(&sms, cudaDevAttrMultiProcessorCount, 0);
    const int grid = sms * 8;   // 2048 threads/SM -> exactly one resident wave

    assemble_kernel<<<grid, TPB>>>(X, Xr, CLS, RING, END, lx, lr, out);
}